// round 1
// baseline (speedup 1.0000x reference)
#include <cuda_runtime.h>

#define FULLMASK 0xffffffffu

namespace {
constexpr int C    = 128;   // channels
constexpr int NHE  = 4;     // heads
constexpr int WS   = 7;     // window size
constexpr int SS   = 3;     // shift size
constexpr int NT   = 49;    // tokens per window
constexpr int HHW  = 112;   // H == W
constexpr int LROW = HHW * HHW;   // 12544 tokens per image

constexpr int SWSTR = 132;  // padded weight-tile row stride (floats)

// shared memory layout (in floats)
constexpr int SX_OFF = 0;                         // 49 x 128 input tile
constexpr int SW_OFF = SX_OFF + NT * C;           // 128 x 132 weight tile
constexpr int SQ_OFF = SW_OFF + C * SWSTR;        // 4 x 49 x 32 (Q, pre-scaled)
constexpr int SK_OFF = SQ_OFF + NHE * NT * 32;    // 4 x 49 x 33 (K, padded)
constexpr int SV_OFF = SK_OFF + NHE * NT * 33;    // 4 x 49 x 33 (V, padded)
constexpr int SO_OFF = SV_OFF + NHE * NT * 33;    // 49 x 128 attn output
constexpr int SMEM_FLOATS = SO_OFF + NT * C + 7 * C;  // + pad for benign overreads
constexpr int SMEM_BYTES  = SMEM_FLOATS * 4;

constexpr float SCALE = 0.17677669529663689f;     // 1/sqrt(32)
}  // namespace

__global__ __launch_bounds__(256, 1)
void swin_block_kernel(const float* __restrict__ x,
                       const float* __restrict__ mask,
                       const float* __restrict__ qkv_w,
                       const float* __restrict__ qkv_b,
                       const float* __restrict__ proj_w,
                       const float* __restrict__ proj_b,
                       const float* __restrict__ rpb,
                       const int*   __restrict__ rel,
                       float* __restrict__ out)
{
    extern __shared__ float sm[];
    float* sX = sm + SX_OFF;
    float* sW = sm + SW_OFF;
    float* sQ = sm + SQ_OFF;
    float* sK = sm + SK_OFF;
    float* sV = sm + SV_OFF;
    float* sO = sm + SO_OFF;

    const int tid  = threadIdx.x;
    const int lane = tid & 31;
    const int warp = tid >> 5;

    const int win  = blockIdx.x;     // 0 .. 2047
    const int b    = win >> 8;       // batch
    const int w256 = win & 255;      // window index within batch
    const int wh   = w256 >> 4;
    const int ww   = w256 & 15;

    // ---------------- Phase 1: gather window tile (roll by -SS folded in) ----
    for (int idx = tid; idx < NT * (C / 4); idx += 256) {
        const int t  = idx >> 5;     // token 0..48
        const int k4 = idx & 31;     // float4 index within row
        const int r  = t / 7;
        const int cc = t - r * 7;
        int gh = wh * WS + r + SS;  if (gh >= HHW) gh -= HHW;
        int gw = ww * WS + cc + SS; if (gw >= HHW) gw -= HHW;
        const float4* src = reinterpret_cast<const float4*>(
            x + (size_t)(b * LROW + gh * HHW + gw) * C);
        reinterpret_cast<float4*>(sX + t * C)[k4] = src[k4];
    }

    // ---------------- Phase 2: QKV GEMM (three 128-feature tiles) ------------
    for (int tile = 0; tile < 3; tile++) {
        __syncthreads();   // prior compute done before overwriting sW (and sX ready)
        const float* wsrc = qkv_w + tile * C * C;
        for (int idx = tid; idx < C * (C / 4); idx += 256) {
            const int f  = idx >> 5;
            const int k4 = idx & 31;
            reinterpret_cast<float4*>(sW + f * SWSTR)[k4] =
                reinterpret_cast<const float4*>(wsrc + f * C)[k4];
        }
        __syncthreads();

        // thread computes tokens m = warp + 8j (j<7), features f = lane + 32i
        float acc[7][4];
        #pragma unroll
        for (int j = 0; j < 7; j++)
            #pragma unroll
            for (int i = 0; i < 4; i++) acc[j][i] = 0.f;

        #pragma unroll 2
        for (int k = 0; k < C; k += 4) {
            const float4 b0 = *reinterpret_cast<const float4*>(sW + (lane     ) * SWSTR + k);
            const float4 b1 = *reinterpret_cast<const float4*>(sW + (lane + 32) * SWSTR + k);
            const float4 b2 = *reinterpret_cast<const float4*>(sW + (lane + 64) * SWSTR + k);
            const float4 b3 = *reinterpret_cast<const float4*>(sW + (lane + 96) * SWSTR + k);
            #pragma unroll
            for (int j = 0; j < 7; j++) {
                const int m = warp + 8 * j;  // may exceed 48; overread is benign, result dropped
                const float4 a = *reinterpret_cast<const float4*>(sX + m * C + k);
                acc[j][0] += a.x * b0.x; acc[j][0] += a.y * b0.y;
                acc[j][0] += a.z * b0.z; acc[j][0] += a.w * b0.w;
                acc[j][1] += a.x * b1.x; acc[j][1] += a.y * b1.y;
                acc[j][1] += a.z * b1.z; acc[j][1] += a.w * b1.w;
                acc[j][2] += a.x * b2.x; acc[j][2] += a.y * b2.y;
                acc[j][2] += a.z * b2.z; acc[j][2] += a.w * b2.w;
                acc[j][3] += a.x * b3.x; acc[j][3] += a.y * b3.y;
                acc[j][3] += a.z * b3.z; acc[j][3] += a.w * b3.w;
            }
        }

        const float bias0 = qkv_b[tile * C + lane];
        const float bias1 = qkv_b[tile * C + lane + 32];
        const float bias2 = qkv_b[tile * C + lane + 64];
        const float bias3 = qkv_b[tile * C + lane + 96];

        // f = lane + 32*i  =>  head = i, d = lane
        #pragma unroll
        for (int j = 0; j < 7; j++) {
            const int m = warp + 8 * j;
            if (m < NT) {
                const float v0 = acc[j][0] + bias0;
                const float v1 = acc[j][1] + bias1;
                const float v2 = acc[j][2] + bias2;
                const float v3 = acc[j][3] + bias3;
                if (tile == 0) {
                    sQ[(0 * NT + m) * 32 + lane] = v0 * SCALE;
                    sQ[(1 * NT + m) * 32 + lane] = v1 * SCALE;
                    sQ[(2 * NT + m) * 32 + lane] = v2 * SCALE;
                    sQ[(3 * NT + m) * 32 + lane] = v3 * SCALE;
                } else if (tile == 1) {
                    sK[(0 * NT + m) * 33 + lane] = v0;
                    sK[(1 * NT + m) * 33 + lane] = v1;
                    sK[(2 * NT + m) * 33 + lane] = v2;
                    sK[(3 * NT + m) * 33 + lane] = v3;
                } else {
                    sV[(0 * NT + m) * 33 + lane] = v0;
                    sV[(1 * NT + m) * 33 + lane] = v1;
                    sV[(2 * NT + m) * 33 + lane] = v2;
                    sV[(3 * NT + m) * 33 + lane] = v3;
                }
            }
        }
    }
    __syncthreads();   // QKV complete; sW free

    // ---- preload proj weights into sW, overlapped with attention compute ----
    for (int idx = tid; idx < C * (C / 4); idx += 256) {
        const int f  = idx >> 5;
        const int k4 = idx & 31;
        reinterpret_cast<float4*>(sW + f * SWSTR)[k4] =
            reinterpret_cast<const float4*>(proj_w + f * C)[k4];
    }

    // ---------------- Phase 3: attention (warp per (head, query-row)) --------
    const float* mbase = mask + (size_t)w256 * NT * NT;
    for (int row = warp; row < NHE * NT; row += 8) {
        const int h = row / NT;
        const int i = row - h * NT;
        const float* qrow = sQ + (h * NT + i) * 32;
        const float* kb   = sK + h * NT * 33;
        const float* vb   = sV + h * NT * 33;

        float s1 = 0.f, s2 = 0.f;   // scores for keys j=lane and j=lane+32
        #pragma unroll
        for (int d = 0; d < 32; d++) {
            const float qd = qrow[d];                       // broadcast LDS
            s1 += qd * kb[lane * 33 + d];                   // conflict-free (pad 33)
            s2 += qd * kb[(lane + 32) * 33 + d];            // benign overread if j2>=49
        }
        const int*   ri   = rel + i * NT;
        const float* mrow = mbase + i * NT;
        const int j2 = lane + 32;
        s1 += rpb[ri[lane] * NHE + h] + mrow[lane];
        if (j2 < NT) s2 += rpb[ri[j2] * NHE + h] + mrow[j2];
        else         s2 = -1e30f;

        float mx = fmaxf(s1, s2);
        #pragma unroll
        for (int o = 16; o; o >>= 1) mx = fmaxf(mx, __shfl_xor_sync(FULLMASK, mx, o));
        float p1 = __expf(s1 - mx);
        float p2 = (j2 < NT) ? __expf(s2 - mx) : 0.f;
        float ssum = p1 + p2;
        #pragma unroll
        for (int o = 16; o; o >>= 1) ssum += __shfl_xor_sync(FULLMASK, ssum, o);
        const float inv = __fdividef(1.f, ssum);
        p1 *= inv; p2 *= inv;

        // PV: lane == output dim d; probabilities broadcast via shuffle
        float oacc = 0.f;
        #pragma unroll
        for (int j = 0; j < 32; j++)
            oacc += __shfl_sync(FULLMASK, p1, j) * vb[j * 33 + lane];
        #pragma unroll
        for (int j = 0; j < 17; j++)
            oacc += __shfl_sync(FULLMASK, p2, j) * vb[(j + 32) * 33 + lane];

        sO[i * C + h * 32 + lane] = oacc;
    }
    __syncthreads();   // sO complete, sW (proj weights) complete

    // ---------------- Phase 4: proj GEMM + scatter back (roll +SS folded) ----
    {
        float acc[7][4];
        #pragma unroll
        for (int j = 0; j < 7; j++)
            #pragma unroll
            for (int i = 0; i < 4; i++) acc[j][i] = 0.f;

        #pragma unroll 2
        for (int k = 0; k < C; k += 4) {
            const float4 b0 = *reinterpret_cast<const float4*>(sW + (lane     ) * SWSTR + k);
            const float4 b1 = *reinterpret_cast<const float4*>(sW + (lane + 32) * SWSTR + k);
            const float4 b2 = *reinterpret_cast<const float4*>(sW + (lane + 64) * SWSTR + k);
            const float4 b3 = *reinterpret_cast<const float4*>(sW + (lane + 96) * SWSTR + k);
            #pragma unroll
            for (int j = 0; j < 7; j++) {
                const int m = warp + 8 * j;
                const float4 a = *reinterpret_cast<const float4*>(sO + m * C + k);
                acc[j][0] += a.x * b0.x; acc[j][0] += a.y * b0.y;
                acc[j][0] += a.z * b0.z; acc[j][0] += a.w * b0.w;
                acc[j][1] += a.x * b1.x; acc[j][1] += a.y * b1.y;
                acc[j][1] += a.z * b1.z; acc[j][1] += a.w * b1.w;
                acc[j][2] += a.x * b2.x; acc[j][2] += a.y * b2.y;
                acc[j][2] += a.z * b2.z; acc[j][2] += a.w * b2.w;
                acc[j][3] += a.x * b3.x; acc[j][3] += a.y * b3.y;
                acc[j][3] += a.z * b3.z; acc[j][3] += a.w * b3.w;
            }
        }

        const float pb0 = proj_b[lane];
        const float pb1 = proj_b[lane + 32];
        const float pb2 = proj_b[lane + 64];
        const float pb3 = proj_b[lane + 96];

        #pragma unroll
        for (int j = 0; j < 7; j++) {
            const int m = warp + 8 * j;
            if (m < NT) {
                const int r  = m / 7;
                const int cc = m - r * 7;
                int gh = wh * WS + r + SS;  if (gh >= HHW) gh -= HHW;
                int gw = ww * WS + cc + SS; if (gw >= HHW) gw -= HHW;
                float* orow = out + (size_t)(b * LROW + gh * HHW + gw) * C;
                orow[lane     ] = acc[j][0] + pb0;
                orow[lane + 32] = acc[j][1] + pb1;
                orow[lane + 64] = acc[j][2] + pb2;
                orow[lane + 96] = acc[j][3] + pb3;
            }
        }
    }
}

extern "C" void kernel_launch(void* const* d_in, const int* in_sizes, int n_in,
                              void* d_out, int out_size)
{
    (void)in_sizes; (void)n_in; (void)out_size;
    const float* x      = (const float*)d_in[0];
    const float* mask   = (const float*)d_in[1];
    const float* qkv_w  = (const float*)d_in[2];
    const float* qkv_b  = (const float*)d_in[3];
    const float* proj_w = (const float*)d_in[4];
    const float* proj_b = (const float*)d_in[5];
    const float* rpb    = (const float*)d_in[6];
    const int*   rel    = (const int*)d_in[7];
    float* out = (float*)d_out;

    cudaFuncSetAttribute(swin_block_kernel,
                         cudaFuncAttributeMaxDynamicSharedMemorySize, SMEM_BYTES);
    swin_block_kernel<<<2048, 256, SMEM_BYTES>>>(
        x, mask, qkv_w, qkv_b, proj_w, proj_b, rpb, rel, out);
}

// round 2
// speedup vs baseline: 1.2074x; 1.2074x over previous
#include <cuda_runtime.h>

#define FULLMASK 0xffffffffu

namespace {
constexpr int C    = 128;   // channels
constexpr int NHE  = 4;     // heads
constexpr int WS   = 7;     // window size
constexpr int SS   = 3;     // shift size
constexpr int NT   = 49;    // tokens per window
constexpr int HHW  = 112;   // H == W
constexpr int LROW = HHW * HHW;   // tokens per image

constexpr int KC     = 16;  // weight K-chunk
constexpr int NCHUNK = C / KC;    // 8
constexpr int WCSTR  = 20;  // padded chunk row stride (floats)

// shared memory layout (floats)
constexpr int SX_OFF  = 0;                          // 49 x 128 input tile (aliased as attn output)
constexpr int SWC_OFF = SX_OFF + NT * C;            // 128 x 20 weight chunk
constexpr int SQ_OFF  = SWC_OFF + C * WCSTR;        // 4 x 49 x 32 (Q, pre-scaled)
constexpr int SK_OFF  = SQ_OFF + NHE * NT * 32;     // 4 x 49 x 33 (K, padded)
constexpr int SV_OFF  = SK_OFF + NHE * NT * 33;     // 4 x 49 x 33 (V, padded)
constexpr int SMEM_FLOATS = SV_OFF + NHE * NT * 33;
constexpr int SMEM_BYTES  = SMEM_FLOATS * 4;        // 112,160 B -> 2 CTAs/SM

constexpr float SCALE = 0.17677669529663689f;       // 1/sqrt(32)
}  // namespace

// Chunked-weight GEMM: out[m][f] = sum_k A[m][k] * W[f][k], A in smem (stride C),
// W from gmem staged through sWc in KC-chunks (software-pipelined).
// Thread computes tokens m = warp + 8j (j<7, clamped) x features f = lane + 32i.
__device__ __forceinline__
void gemm_chunked(const float* __restrict__ sA, float* __restrict__ sWc,
                  const float* __restrict__ wsrc,
                  int warp, int lane, int tid, float acc[7][4])
{
    #pragma unroll
    for (int j = 0; j < 7; j++)
        #pragma unroll
        for (int i = 0; i < 4; i++) acc[j][i] = 0.f;

    // clamped A-row pointers (dup rows computed, results dropped later)
    const float* aptr[7];
    #pragma unroll
    for (int j = 0; j < 7; j++) {
        int m = warp + 8 * j; if (m > NT - 1) m = NT - 1;
        aptr[j] = sA + m * C;
    }

    // per-thread staging slots: idx = tid + 256*r, f = idx>>2, q = idx&3
    const int f0 = (tid      ) >> 2, q0 = (tid      ) & 3;
    const int f1 = (tid + 256) >> 2, q1 = (tid + 256) & 3;

    float4 w0 = *reinterpret_cast<const float4*>(wsrc + f0 * C + q0 * 4);
    float4 w1 = *reinterpret_cast<const float4*>(wsrc + f1 * C + q1 * 4);

    for (int ch = 0; ch < NCHUNK; ch++) {
        __syncthreads();   // previous chunk compute finished reading sWc
        *reinterpret_cast<float4*>(sWc + f0 * WCSTR + q0 * 4) = w0;
        *reinterpret_cast<float4*>(sWc + f1 * WCSTR + q1 * 4) = w1;
        __syncthreads();

        if (ch < NCHUNK - 1) {   // prefetch next chunk (overlaps compute)
            const float* nw = wsrc + (ch + 1) * KC;
            w0 = *reinterpret_cast<const float4*>(nw + f0 * C + q0 * 4);
            w1 = *reinterpret_cast<const float4*>(nw + f1 * C + q1 * 4);
        }

        const int kb = ch * KC;
        #pragma unroll
        for (int kk = 0; kk < KC; kk += 4) {
            const float4 b0 = *reinterpret_cast<const float4*>(sWc + (lane     ) * WCSTR + kk);
            const float4 b1 = *reinterpret_cast<const float4*>(sWc + (lane + 32) * WCSTR + kk);
            const float4 b2 = *reinterpret_cast<const float4*>(sWc + (lane + 64) * WCSTR + kk);
            const float4 b3 = *reinterpret_cast<const float4*>(sWc + (lane + 96) * WCSTR + kk);
            #pragma unroll
            for (int j = 0; j < 7; j++) {
                const float4 a = *reinterpret_cast<const float4*>(aptr[j] + kb + kk);
                acc[j][0] += a.x * b0.x; acc[j][0] += a.y * b0.y;
                acc[j][0] += a.z * b0.z; acc[j][0] += a.w * b0.w;
                acc[j][1] += a.x * b1.x; acc[j][1] += a.y * b1.y;
                acc[j][1] += a.z * b1.z; acc[j][1] += a.w * b1.w;
                acc[j][2] += a.x * b2.x; acc[j][2] += a.y * b2.y;
                acc[j][2] += a.z * b2.z; acc[j][2] += a.w * b2.w;
                acc[j][3] += a.x * b3.x; acc[j][3] += a.y * b3.y;
                acc[j][3] += a.z * b3.z; acc[j][3] += a.w * b3.w;
            }
        }
    }
}

__global__ __launch_bounds__(256, 2)
void swin_block_kernel(const float* __restrict__ x,
                       const float* __restrict__ mask,
                       const float* __restrict__ qkv_w,
                       const float* __restrict__ qkv_b,
                       const float* __restrict__ proj_w,
                       const float* __restrict__ proj_b,
                       const float* __restrict__ rpb,
                       const int*   __restrict__ rel,
                       float* __restrict__ out)
{
    extern __shared__ float sm[];
    float* sX  = sm + SX_OFF;       // input tile; later aliased as attn output sO
    float* sWc = sm + SWC_OFF;
    float* sQ  = sm + SQ_OFF;
    float* sK  = sm + SK_OFF;
    float* sV  = sm + SV_OFF;

    const int tid  = threadIdx.x;
    const int lane = tid & 31;
    const int warp = tid >> 5;

    const int win  = blockIdx.x;     // 0 .. 2047
    const int b    = win >> 8;
    const int w256 = win & 255;
    const int wh   = w256 >> 4;
    const int ww   = w256 & 15;

    // ---------------- Phase 1: gather window tile (roll by -SS folded in) ----
    for (int idx = tid; idx < NT * (C / 4); idx += 256) {
        const int t  = idx >> 5;
        const int k4 = idx & 31;
        const int r  = t / 7;
        const int cc = t - r * 7;
        int gh = wh * WS + r + SS;  if (gh >= HHW) gh -= HHW;
        int gw = ww * WS + cc + SS; if (gw >= HHW) gw -= HHW;
        const float4* src = reinterpret_cast<const float4*>(
            x + (size_t)(b * LROW + gh * HHW + gw) * C);
        reinterpret_cast<float4*>(sX + t * C)[k4] = src[k4];
    }
    __syncthreads();

    // ---------------- Phase 2: QKV GEMM (three 128-feature tiles) ------------
    for (int tile = 0; tile < 3; tile++) {
        float acc[7][4];
        gemm_chunked(sX, sWc, qkv_w + tile * C * C, warp, lane, tid, acc);

        const float bias0 = __ldg(qkv_b + tile * C + lane);
        const float bias1 = __ldg(qkv_b + tile * C + lane + 32);
        const float bias2 = __ldg(qkv_b + tile * C + lane + 64);
        const float bias3 = __ldg(qkv_b + tile * C + lane + 96);

        // f = lane + 32*i  =>  head = i, d = lane
        #pragma unroll
        for (int j = 0; j < 7; j++) {
            const int m = warp + 8 * j;
            if (m < NT) {
                const float v0 = acc[j][0] + bias0;
                const float v1 = acc[j][1] + bias1;
                const float v2 = acc[j][2] + bias2;
                const float v3 = acc[j][3] + bias3;
                if (tile == 0) {
                    sQ[(0 * NT + m) * 32 + lane] = v0 * SCALE;
                    sQ[(1 * NT + m) * 32 + lane] = v1 * SCALE;
                    sQ[(2 * NT + m) * 32 + lane] = v2 * SCALE;
                    sQ[(3 * NT + m) * 32 + lane] = v3 * SCALE;
                } else if (tile == 1) {
                    sK[(0 * NT + m) * 33 + lane] = v0;
                    sK[(1 * NT + m) * 33 + lane] = v1;
                    sK[(2 * NT + m) * 33 + lane] = v2;
                    sK[(3 * NT + m) * 33 + lane] = v3;
                } else {
                    sV[(0 * NT + m) * 33 + lane] = v0;
                    sV[(1 * NT + m) * 33 + lane] = v1;
                    sV[(2 * NT + m) * 33 + lane] = v2;
                    sV[(3 * NT + m) * 33 + lane] = v3;
                }
            }
        }
    }
    __syncthreads();   // Q/K/V complete; sX free -> becomes sO

    float* sO = sX;

    // ---------------- Phase 3: attention (warp per (head, query-row)) --------
    const float* mbase = mask + (size_t)w256 * NT * NT;
    for (int row = warp; row < NHE * NT; row += 8) {
        const int h = row / NT;
        const int i = row - h * NT;
        const float* kb = sK + h * NT * 33;
        const float* vb = sV + h * NT * 33;

        // hoist q row into registers (broadcast float4 LDS)
        float4 q4[8];
        {
            const float4* qrow = reinterpret_cast<const float4*>(sQ + (h * NT + i) * 32);
            #pragma unroll
            for (int u = 0; u < 8; u++) q4[u] = qrow[u];
        }

        float s1 = 0.f, s2 = 0.f;
        const float* k1 = kb + lane * 33;
        const float* k2 = kb + (lane + 32) * 33;   // overreads into sV for j2>=49; finite, discarded
        #pragma unroll
        for (int u = 0; u < 8; u++) {
            s1 += q4[u].x * k1[4 * u    ]; s2 += q4[u].x * k2[4 * u    ];
            s1 += q4[u].y * k1[4 * u + 1]; s2 += q4[u].y * k2[4 * u + 1];
            s1 += q4[u].z * k1[4 * u + 2]; s2 += q4[u].z * k2[4 * u + 2];
            s1 += q4[u].w * k1[4 * u + 3]; s2 += q4[u].w * k2[4 * u + 3];
        }
        const int*   ri   = rel + i * NT;
        const float* mrow = mbase + i * NT;
        const int j2 = lane + 32;
        s1 += __ldg(rpb + __ldg(ri + lane) * NHE + h) + __ldg(mrow + lane);
        if (j2 < NT) s2 += __ldg(rpb + __ldg(ri + j2) * NHE + h) + __ldg(mrow + j2);
        else         s2 = -1e30f;

        float mx = fmaxf(s1, s2);
        #pragma unroll
        for (int o = 16; o; o >>= 1) mx = fmaxf(mx, __shfl_xor_sync(FULLMASK, mx, o));
        float p1 = __expf(s1 - mx);
        float p2 = (j2 < NT) ? __expf(s2 - mx) : 0.f;
        float ssum = p1 + p2;
        #pragma unroll
        for (int o = 16; o; o >>= 1) ssum += __shfl_xor_sync(FULLMASK, ssum, o);
        const float inv = __fdividef(1.f, ssum);
        p1 *= inv; p2 *= inv;

        // PV: lane == output dim d; probabilities broadcast via shuffle
        float oacc = 0.f;
        #pragma unroll
        for (int j = 0; j < 32; j++)
            oacc += __shfl_sync(FULLMASK, p1, j) * vb[j * 33 + lane];
        #pragma unroll
        for (int j = 0; j < 17; j++)
            oacc += __shfl_sync(FULLMASK, p2, j) * vb[(j + 32) * 33 + lane];

        sO[i * C + h * 32 + lane] = oacc;
    }
    __syncthreads();   // sO complete

    // ---------------- Phase 4: proj GEMM + scatter back (roll +SS folded) ----
    {
        float acc[7][4];
        gemm_chunked(sO, sWc, proj_w, warp, lane, tid, acc);

        const float pb0 = __ldg(proj_b + lane);
        const float pb1 = __ldg(proj_b + lane + 32);
        const float pb2 = __ldg(proj_b + lane + 64);
        const float pb3 = __ldg(proj_b + lane + 96);

        #pragma unroll
        for (int j = 0; j < 7; j++) {
            const int m = warp + 8 * j;
            if (m < NT) {
                const int r  = m / 7;
                const int cc = m - r * 7;
                int gh = wh * WS + r + SS;  if (gh >= HHW) gh -= HHW;
                int gw = ww * WS + cc + SS; if (gw >= HHW) gw -= HHW;
                float* orow = out + (size_t)(b * LROW + gh * HHW + gw) * C;
                orow[lane     ] = acc[j][0] + pb0;
                orow[lane + 32] = acc[j][1] + pb1;
                orow[lane + 64] = acc[j][2] + pb2;
                orow[lane + 96] = acc[j][3] + pb3;
            }
        }
    }
}

extern "C" void kernel_launch(void* const* d_in, const int* in_sizes, int n_in,
                              void* d_out, int out_size)
{
    (void)in_sizes; (void)n_in; (void)out_size;
    const float* x      = (const float*)d_in[0];
    const float* mask   = (const float*)d_in[1];
    const float* qkv_w  = (const float*)d_in[2];
    const float* qkv_b  = (const float*)d_in[3];
    const float* proj_w = (const float*)d_in[4];
    const float* proj_b = (const float*)d_in[5];
    const float* rpb    = (const float*)d_in[6];
    const int*   rel    = (const int*)d_in[7];
    float* out = (float*)d_out;

    cudaFuncSetAttribute(swin_block_kernel,
                         cudaFuncAttributeMaxDynamicSharedMemorySize, SMEM_BYTES);
    swin_block_kernel<<<2048, 256, SMEM_BYTES>>>(
        x, mask, qkv_w, qkv_b, proj_w, proj_b, rpb, rel, out);
}

// round 3
// speedup vs baseline: 1.5128x; 1.2530x over previous
#include <cuda_runtime.h>
#include <cstdint>

#define FULLMASK 0xffffffffu

namespace {
constexpr int C    = 128;
constexpr int NHE  = 4;
constexpr int WS   = 7;
constexpr int SS   = 3;
constexpr int NT   = 49;
constexpr int HHW  = 112;
constexpr int LROW = HHW * HHW;

constexpr int AST   = 132;   // sX / sO row stride (A fragments conflict-free)
constexpr int KC    = 16;    // weight K-chunk
constexpr int NCH   = 8;     // chunks per GEMM
constexpr int WCSTR = 20;    // weight chunk row stride (B fragments conflict-free)
constexpr int QST   = 32;
constexpr int KST   = 33;
constexpr int VST   = 33;
constexpr int OST   = 132;   // proj-output staging stride (lives in sK region)

// shared memory layout (floats)
constexpr int SX_OFF  = 0;                        // 49 x 132
constexpr int SWC_OFF = SX_OFF + NT * AST;        // 128 x 20
constexpr int SQ_OFF  = SWC_OFF + C * WCSTR;      // 4 x 49 x 32
constexpr int SK_OFF  = SQ_OFF + NHE * NT * QST;  // 4 x 49 x 33 (reused as proj staging)
constexpr int SV_OFF  = SK_OFF + NHE * NT * KST;  // 4 x 49 x 33
constexpr int SMEM_FLOATS = SV_OFF + NHE * NT * VST;
constexpr int SMEM_BYTES  = SMEM_FLOATS * 4;      // 112,944 B -> 2 CTAs/SM

constexpr float SCALE = 0.17677669529663689f;     // 1/sqrt(32)
}  // namespace

__device__ __forceinline__ float tf32r(float f) {
    uint32_t u;
    asm("cvt.rna.tf32.f32 %0, %1;" : "=r"(u) : "f"(f));
    return __uint_as_float(u);
}
__device__ __forceinline__ float4 tf32r4(float4 v) {
    v.x = tf32r(v.x); v.y = tf32r(v.y); v.z = tf32r(v.z); v.w = tf32r(v.w);
    return v;
}

__device__ __forceinline__
void mma_tf32(float4& d, uint32_t a0, uint32_t a1, uint32_t a2, uint32_t a3,
              uint32_t b0, uint32_t b1)
{
    asm volatile(
        "mma.sync.aligned.m16n8k8.row.col.f32.tf32.tf32.f32 "
        "{%0,%1,%2,%3}, {%4,%5,%6,%7}, {%8,%9}, {%0,%1,%2,%3};\n"
        : "+f"(d.x), "+f"(d.y), "+f"(d.z), "+f"(d.w)
        : "r"(a0), "r"(a1), "r"(a2), "r"(a3), "r"(b0), "r"(b1));
}

// 49x128 @ 128x128^T GEMM on tensor cores.
// A in smem (tf32-rounded, stride AST). W[f][k] streamed from gmem in KC-chunks.
// Warp w: m_tile = w&3 (rows m_tile*16..+15), n-half = (w>>2)*64, 8 n-tiles of 8.
__device__ __forceinline__
void gemm_mma(const float* __restrict__ sA, float* __restrict__ sWc,
              const float* __restrict__ wsrc,
              int warp, int lane, int tid, float4 acc[8])
{
    #pragma unroll
    for (int t = 0; t < 8; t++) acc[t] = make_float4(0.f, 0.f, 0.f, 0.f);

    const int mt  = warp & 3;
    const int n0  = (warp >> 2) * 64;
    const int gid = lane >> 2;
    const int tig = lane & 3;

    int r1 = mt * 16 + gid;     if (r1 > NT - 1) r1 = NT - 1;
    int r2 = mt * 16 + gid + 8; if (r2 > NT - 1) r2 = NT - 1;
    const float* a1p = sA + r1 * AST + tig;
    const float* a2p = sA + r2 * AST + tig;

    // staging: granule i -> f = i>>2 (row), q4 = i&3 (float4 within 16-col chunk)
    const float4* wsrc4 = reinterpret_cast<const float4*>(wsrc);  // 32 float4 per row
    const int f0 = tid >> 2,        q0 = tid & 3;
    const int f1 = 64 + (tid >> 2), q1 = tid & 3;

    float4 w0 = wsrc4[f0 * 32 + q0];
    float4 w1 = wsrc4[f1 * 32 + q1];

    for (int ch = 0; ch < NCH; ch++) {
        __syncthreads();   // all warps done reading previous sWc contents
        *reinterpret_cast<float4*>(sWc + f0 * WCSTR + q0 * 4) = tf32r4(w0);
        *reinterpret_cast<float4*>(sWc + f1 * WCSTR + q1 * 4) = tf32r4(w1);
        __syncthreads();

        if (ch < NCH - 1) {  // prefetch next chunk, overlaps compute
            w0 = wsrc4[f0 * 32 + (ch + 1) * 4 + q0];
            w1 = wsrc4[f1 * 32 + (ch + 1) * 4 + q1];
        }

        const int kb = ch * KC;
        #pragma unroll
        for (int kk = 0; kk < 2; kk++) {
            const int k0 = kb + kk * 8;
            const uint32_t a0 = __float_as_uint(a1p[k0]);
            const uint32_t a1 = __float_as_uint(a2p[k0]);
            const uint32_t a2 = __float_as_uint(a1p[k0 + 4]);
            const uint32_t a3 = __float_as_uint(a2p[k0 + 4]);
            #pragma unroll
            for (int t = 0; t < 8; t++) {
                const float* bp = sWc + (n0 + t * 8 + gid) * WCSTR + kk * 8 + tig;
                const uint32_t b0 = __float_as_uint(bp[0]);
                const uint32_t b1 = __float_as_uint(bp[4]);
                mma_tf32(acc[t], a0, a1, a2, a3, b0, b1);
            }
        }
    }
}

__global__ __launch_bounds__(256, 2)
void swin_block_kernel(const float* __restrict__ x,
                       const float* __restrict__ mask,
                       const float* __restrict__ qkv_w,
                       const float* __restrict__ qkv_b,
                       const float* __restrict__ proj_w,
                       const float* __restrict__ proj_b,
                       const float* __restrict__ rpb,
                       const int*   __restrict__ rel,
                       float* __restrict__ out)
{
    extern __shared__ float sm[];
    float* sX  = sm + SX_OFF;    // input tile (tf32); later attn output sO
    float* sWc = sm + SWC_OFF;
    float* sQ  = sm + SQ_OFF;
    float* sK  = sm + SK_OFF;    // later: proj-output staging
    float* sV  = sm + SV_OFF;

    const int tid  = threadIdx.x;
    const int lane = tid & 31;
    const int warp = tid >> 5;
    const int gid  = lane >> 2;
    const int tig  = lane & 3;

    const int win  = blockIdx.x;
    const int b    = win >> 8;
    const int w256 = win & 255;
    const int wh   = w256 >> 4;
    const int ww   = w256 & 15;

    // ---------------- Phase 1: gather window (roll -SS folded), round to tf32
    for (int idx = tid; idx < NT * (C / 4); idx += 256) {
        const int t  = idx >> 5;
        const int k4 = idx & 31;
        const int r  = t / 7;
        const int cc = t - r * 7;
        int gh = wh * WS + r + SS;  if (gh >= HHW) gh -= HHW;
        int gw = ww * WS + cc + SS; if (gw >= HHW) gw -= HHW;
        const float4 v = reinterpret_cast<const float4*>(
            x + (size_t)(b * LROW + gh * HHW + gw) * C)[k4];
        *reinterpret_cast<float4*>(sX + t * AST + k4 * 4) = tf32r4(v);
    }

    const int m1 = (warp & 3) * 16 + gid;
    const int m2 = m1 + 8;
    const int nn0 = (warp >> 2) * 64;

    // ---------------- Phase 2: QKV on tensor cores ----------------------------
    for (int tile = 0; tile < 3; tile++) {
        float4 acc[8];
        gemm_mma(sX, sWc, qkv_w + tile * C * C, warp, lane, tid, acc);

        const float* bias = qkv_b + tile * C;
        if (tile == 0) {
            #pragma unroll
            for (int t = 0; t < 8; t++) {
                const int ne = nn0 + t * 8 + 2 * tig;       // even col, head = ne>>5
                const float be = __ldg(bias + ne);
                const float bo = __ldg(bias + ne + 1);
                float* qb = sQ + ((ne >> 5) * NT) * QST + (ne & 31);
                if (m1 < NT)
                    *reinterpret_cast<float2*>(qb + m1 * QST) =
                        make_float2((acc[t].x + be) * SCALE, (acc[t].y + bo) * SCALE);
                if (m2 < NT)
                    *reinterpret_cast<float2*>(qb + m2 * QST) =
                        make_float2((acc[t].z + be) * SCALE, (acc[t].w + bo) * SCALE);
            }
        } else {
            float* dst = (tile == 1) ? sK : sV;
            const int str = (tile == 1) ? KST : VST;
            #pragma unroll
            for (int t = 0; t < 8; t++) {
                const int ne = nn0 + t * 8 + 2 * tig;
                const float be = __ldg(bias + ne);
                const float bo = __ldg(bias + ne + 1);
                float* db = dst + ((ne >> 5) * NT) * str + (ne & 31);
                if (m1 < NT) {
                    db[m1 * str]     = acc[t].x + be;
                    db[m1 * str + 1] = acc[t].y + bo;
                }
                if (m2 < NT) {
                    db[m2 * str]     = acc[t].z + be;
                    db[m2 * str + 1] = acc[t].w + bo;
                }
            }
        }
    }
    __syncthreads();   // Q/K/V ready; sX free -> sO

    float* sO = sX;

    // ---------------- Phase 3: attention (warp per (head, query-row)) --------
    const float* mbase = mask + (size_t)w256 * NT * NT;
    for (int row = warp; row < NHE * NT; row += 8) {
        const int h = row / NT;
        const int i = row - h * NT;
        const float* kb = sK + h * NT * KST;
        const float* vb = sV + h * NT * VST;

        float4 q4[8];
        {
            const float4* qrow = reinterpret_cast<const float4*>(sQ + (h * NT + i) * QST);
            #pragma unroll
            for (int u = 0; u < 8; u++) q4[u] = qrow[u];
        }

        float s1 = 0.f, s2 = 0.f;
        const float* k1 = kb + lane * KST;
        const float* k2 = kb + (lane + 32) * KST;   // overread into sV region: finite, dropped
        #pragma unroll
        for (int u = 0; u < 8; u++) {
            s1 += q4[u].x * k1[4 * u    ]; s2 += q4[u].x * k2[4 * u    ];
            s1 += q4[u].y * k1[4 * u + 1]; s2 += q4[u].y * k2[4 * u + 1];
            s1 += q4[u].z * k1[4 * u + 2]; s2 += q4[u].z * k2[4 * u + 2];
            s1 += q4[u].w * k1[4 * u + 3]; s2 += q4[u].w * k2[4 * u + 3];
        }
        const int*   ri   = rel + i * NT;
        const float* mrow = mbase + i * NT;
        const int j2 = lane + 32;
        s1 += __ldg(rpb + __ldg(ri + lane) * NHE + h) + __ldg(mrow + lane);
        if (j2 < NT) s2 += __ldg(rpb + __ldg(ri + j2) * NHE + h) + __ldg(mrow + j2);
        else         s2 = -1e30f;

        float mx = fmaxf(s1, s2);
        #pragma unroll
        for (int o = 16; o; o >>= 1) mx = fmaxf(mx, __shfl_xor_sync(FULLMASK, mx, o));
        float p1 = __expf(s1 - mx);
        float p2 = (j2 < NT) ? __expf(s2 - mx) : 0.f;
        float ssum = p1 + p2;
        #pragma unroll
        for (int o = 16; o; o >>= 1) ssum += __shfl_xor_sync(FULLMASK, ssum, o);
        const float inv = __fdividef(1.f, ssum);
        p1 *= inv; p2 *= inv;

        float oacc = 0.f;
        #pragma unroll
        for (int j = 0; j < 32; j++)
            oacc += __shfl_sync(FULLMASK, p1, j) * vb[j * VST + lane];
        #pragma unroll
        for (int j = 0; j < 17; j++)
            oacc += __shfl_sync(FULLMASK, p2, j) * vb[(j + 32) * VST + lane];

        sO[i * AST + h * 32 + lane] = tf32r(oacc);
    }

    // ---------------- Phase 4: proj GEMM on tensor cores ---------------------
    float4 acc[8];
    gemm_mma(sO, sWc, proj_w, warp, lane, tid, acc);   // starts with __syncthreads

    // stage into sK region (dead now), stride OST, then coalesced writeback
    float* sOut = sK;
    #pragma unroll
    for (int t = 0; t < 8; t++) {
        const int ne = nn0 + t * 8 + 2 * tig;
        if (m1 < NT)
            *reinterpret_cast<float2*>(sOut + m1 * OST + ne) = make_float2(acc[t].x, acc[t].y);
        if (m2 < NT)
            *reinterpret_cast<float2*>(sOut + m2 * OST + ne) = make_float2(acc[t].z, acc[t].w);
    }
    __syncthreads();

    // ---------------- Phase 5: add bias, scatter back (roll +SS folded) ------
    for (int idx = tid; idx < NT * (C / 4); idx += 256) {
        const int t  = idx >> 5;
        const int k4 = idx & 31;
        const int r  = t / 7;
        const int cc = t - r * 7;
        int gh = wh * WS + r + SS;  if (gh >= HHW) gh -= HHW;
        int gw = ww * WS + cc + SS; if (gw >= HHW) gw -= HHW;
        float4 v = *reinterpret_cast<const float4*>(sOut + t * OST + k4 * 4);
        const float4 pb = reinterpret_cast<const float4*>(proj_b)[k4];
        v.x += pb.x; v.y += pb.y; v.z += pb.z; v.w += pb.w;
        reinterpret_cast<float4*>(out + (size_t)(b * LROW + gh * HHW + gw) * C)[k4] = v;
    }
}

extern "C" void kernel_launch(void* const* d_in, const int* in_sizes, int n_in,
                              void* d_out, int out_size)
{
    (void)in_sizes; (void)n_in; (void)out_size;
    const float* x      = (const float*)d_in[0];
    const float* mask   = (const float*)d_in[1];
    const float* qkv_w  = (const float*)d_in[2];
    const float* qkv_b  = (const float*)d_in[3];
    const float* proj_w = (const float*)d_in[4];
    const float* proj_b = (const float*)d_in[5];
    const float* rpb    = (const float*)d_in[6];
    const int*   rel    = (const int*)d_in[7];
    float* out = (float*)d_out;

    cudaFuncSetAttribute(swin_block_kernel,
                         cudaFuncAttributeMaxDynamicSharedMemorySize, SMEM_BYTES);
    swin_block_kernel<<<2048, 256, SMEM_BYTES>>>(
        x, mask, qkv_w, qkv_b, proj_w, proj_b, rpb, rel, out);
}

// round 4
// speedup vs baseline: 2.7230x; 1.7999x over previous
#include <cuda_runtime.h>
#include <cstdint>

#define FULLMASK 0xffffffffu

namespace {
constexpr int C    = 128;
constexpr int NHE  = 4;
constexpr int WS   = 7;
constexpr int SS   = 3;
constexpr int NT   = 49;
constexpr int HHW  = 112;
constexpr int LROW = HHW * HHW;

constexpr int AST   = 132;   // sX / sO row stride (A fragments conflict-free)
constexpr int KCH   = 16;    // weight K-chunk
constexpr int NCH   = 8;     // chunks per GEMM
constexpr int WCSTR = 20;    // weight chunk row stride
constexpr int QKST  = 36;    // sQ / sK row stride (frag conflict-free)
constexpr int VTST  = 60;    // sVt row stride (frag conflict-free)

// shared memory layout (floats)
constexpr int SX_OFF = 0;                         // 49 x 132 (input tile / attn out)
constexpr int SH_OFF = SX_OFF + NT * AST;         // shared region: sWc (128x20=2560) / sVt (4*32*60=7680)
constexpr int SH_SZ  = NHE * 32 * VTST;           // 7680
constexpr int SQ_OFF = SH_OFF + SH_SZ;            // 196 x 36
constexpr int SK_OFF = SQ_OFF + 196 * QKST;       // 196 x 36 (reused as proj staging)
constexpr int SMEM_FLOATS = SK_OFF + 196 * QKST;  // 28260 floats
constexpr int SMEM_BYTES  = SMEM_FLOATS * 4;      // 113,040 B -> 2 CTAs/SM

constexpr float SCALE = 0.17677669529663689f;     // 1/sqrt(32)

constexpr int CB_I = 64;   // padded rows
constexpr int CB_J = 56;   // padded cols
constexpr int CB_TOT = 256 * NHE * CB_I * CB_J;   // 3,670,016
}  // namespace

__device__ float g_cb[CB_TOT];   // combined (mask + rel-pos bias) per window class

__device__ __forceinline__ float tf32r(float f) {
    uint32_t u;
    asm("cvt.rna.tf32.f32 %0, %1;" : "=r"(u) : "f"(f));
    return __uint_as_float(u);
}
__device__ __forceinline__ float4 tf32r4(float4 v) {
    v.x = tf32r(v.x); v.y = tf32r(v.y); v.z = tf32r(v.z); v.w = tf32r(v.w);
    return v;
}

__device__ __forceinline__
void mma_tf32(float4& d, uint32_t a0, uint32_t a1, uint32_t a2, uint32_t a3,
              uint32_t b0, uint32_t b1)
{
    asm volatile(
        "mma.sync.aligned.m16n8k8.row.col.f32.tf32.tf32.f32 "
        "{%0,%1,%2,%3}, {%4,%5,%6,%7}, {%8,%9}, {%0,%1,%2,%3};\n"
        : "+f"(d.x), "+f"(d.y), "+f"(d.z), "+f"(d.w)
        : "r"(a0), "r"(a1), "r"(a2), "r"(a3), "r"(b0), "r"(b1));
}

// ---------------- bias precompute: g_cb[w][h][i][j] ----------------
__global__ void cb_precompute(const float* __restrict__ mask,
                              const float* __restrict__ rpb,
                              const int*   __restrict__ rel)
{
    const int idx = blockIdx.x * blockDim.x + threadIdx.x;
    if (idx >= CB_TOT) return;
    const int j = idx % CB_J;
    int r = idx / CB_J;
    const int i = r % CB_I;  r /= CB_I;
    const int h = r % NHE;
    const int w = r / NHE;
    float v;
    if (j >= NT)      v = -1e30f;                 // masks N padding -> p = 0
    else if (i >= NT) v = 0.f;                    // dropped rows, keep finite
    else v = mask[(w * NT + i) * NT + j] + rpb[rel[i * NT + j] * NHE + h];
    g_cb[idx] = v;
}

// 49x128 @ 128x128^T GEMM on tensor cores (A smem tf32, W streamed in chunks)
__device__ __forceinline__
void gemm_mma(const float* __restrict__ sA, float* __restrict__ sWc,
              const float* __restrict__ wsrc,
              int warp, int lane, int tid, float4 acc[8])
{
    #pragma unroll
    for (int t = 0; t < 8; t++) acc[t] = make_float4(0.f, 0.f, 0.f, 0.f);

    const int mt  = warp & 3;
    const int n0  = (warp >> 2) * 64;
    const int gid = lane >> 2;
    const int tig = lane & 3;

    int r1 = mt * 16 + gid;     if (r1 > NT - 1) r1 = NT - 1;
    int r2 = mt * 16 + gid + 8; if (r2 > NT - 1) r2 = NT - 1;
    const float* a1p = sA + r1 * AST + tig;
    const float* a2p = sA + r2 * AST + tig;

    const float4* wsrc4 = reinterpret_cast<const float4*>(wsrc);
    const int f0 = tid >> 2,        q0 = tid & 3;
    const int f1 = 64 + (tid >> 2), q1 = tid & 3;

    float4 w0 = wsrc4[f0 * 32 + q0];
    float4 w1 = wsrc4[f1 * 32 + q1];

    for (int ch = 0; ch < NCH; ch++) {
        __syncthreads();
        *reinterpret_cast<float4*>(sWc + f0 * WCSTR + q0 * 4) = tf32r4(w0);
        *reinterpret_cast<float4*>(sWc + f1 * WCSTR + q1 * 4) = tf32r4(w1);
        __syncthreads();

        if (ch < NCH - 1) {
            w0 = wsrc4[f0 * 32 + (ch + 1) * 4 + q0];
            w1 = wsrc4[f1 * 32 + (ch + 1) * 4 + q1];
        }

        const int kb = ch * KCH;
        #pragma unroll
        for (int kk = 0; kk < 2; kk++) {
            const int k0 = kb + kk * 8;
            const uint32_t a0 = __float_as_uint(a1p[k0]);
            const uint32_t a1 = __float_as_uint(a2p[k0]);
            const uint32_t a2 = __float_as_uint(a1p[k0 + 4]);
            const uint32_t a3 = __float_as_uint(a2p[k0 + 4]);
            #pragma unroll
            for (int t = 0; t < 8; t++) {
                const float* bp = sWc + (n0 + t * 8 + gid) * WCSTR + kk * 8 + tig;
                mma_tf32(acc[t], a0, a1, a2, a3,
                         __float_as_uint(bp[0]), __float_as_uint(bp[4]));
            }
        }
    }
}

__global__ __launch_bounds__(256, 2)
void swin_block_kernel(const float* __restrict__ x,
                       const float* __restrict__ qkv_w,
                       const float* __restrict__ qkv_b,
                       const float* __restrict__ proj_w,
                       const float* __restrict__ proj_b,
                       float* __restrict__ out)
{
    extern __shared__ float sm[];
    float* sX  = sm + SX_OFF;    // input tile; later attn output sO
    float* sWc = sm + SH_OFF;    // GEMM weight chunk (aliases sVt)
    float* sVt = sm + SH_OFF;    // V transposed [h][d][j], stride VTST
    float* sQ  = sm + SQ_OFF;    // [h*49+m][d], stride QKST
    float* sK  = sm + SK_OFF;    // [h*49+j][d], stride QKST; later proj staging

    const int tid  = threadIdx.x;
    const int lane = tid & 31;
    const int warp = tid >> 5;
    const int gid  = lane >> 2;
    const int tig  = lane & 3;

    const int win  = blockIdx.x;
    const int b    = win >> 8;
    const int w256 = win & 255;
    const int wh   = w256 >> 4;
    const int ww   = w256 & 15;

    // ---------------- Phase 1: gather window (roll -SS), round to tf32 ------
    for (int idx = tid; idx < NT * (C / 4); idx += 256) {
        const int t  = idx >> 5;
        const int k4 = idx & 31;
        const int r  = t / 7;
        const int cc = t - r * 7;
        int gh = wh * WS + r + SS;  if (gh >= HHW) gh -= HHW;
        int gw = ww * WS + cc + SS; if (gw >= HHW) gw -= HHW;
        const float4 v = reinterpret_cast<const float4*>(
            x + (size_t)(b * LROW + gh * HHW + gw) * C)[k4];
        *reinterpret_cast<float4*>(sX + t * AST + k4 * 4) = tf32r4(v);
    }

    const int m1  = (warp & 3) * 16 + gid;
    const int m2  = m1 + 8;
    const int nn0 = (warp >> 2) * 64;

    // ---------------- Phase 2: QKV on tensor cores ---------------------------
    for (int tile = 0; tile < 3; tile++) {
        float4 acc[8];
        gemm_mma(sX, sWc, qkv_w + tile * C * C, warp, lane, tid, acc);

        if (tile == 2) __syncthreads();   // sVt aliases sWc: wait for all B-frag reads

        const float* bias = qkv_b + tile * C;
        #pragma unroll
        for (int t = 0; t < 8; t++) {
            const int ne = nn0 + t * 8 + 2 * tig;
            const int h  = ne >> 5;
            const int d  = ne & 31;
            const float be = __ldg(bias + ne);
            const float bo = __ldg(bias + ne + 1);
            if (tile == 0) {
                float* qb = sQ + (h * NT) * QKST + d;
                if (m1 < NT)
                    *reinterpret_cast<float2*>(qb + m1 * QKST) =
                        make_float2(tf32r((acc[t].x + be) * SCALE), tf32r((acc[t].y + bo) * SCALE));
                if (m2 < NT)
                    *reinterpret_cast<float2*>(qb + m2 * QKST) =
                        make_float2(tf32r((acc[t].z + be) * SCALE), tf32r((acc[t].w + bo) * SCALE));
            } else if (tile == 1) {
                float* kb = sK + (h * NT) * QKST + d;
                if (m1 < NT)
                    *reinterpret_cast<float2*>(kb + m1 * QKST) =
                        make_float2(tf32r(acc[t].x + be), tf32r(acc[t].y + bo));
                if (m2 < NT)
                    *reinterpret_cast<float2*>(kb + m2 * QKST) =
                        make_float2(tf32r(acc[t].z + be), tf32r(acc[t].w + bo));
            } else {
                float* v0 = sVt + (h * 32 + d) * VTST;
                float* v1 = sVt + (h * 32 + d + 1) * VTST;
                if (m1 < NT) {
                    v0[m1] = tf32r(acc[t].x + be);
                    v1[m1] = tf32r(acc[t].y + bo);
                }
                if (m2 < NT) {
                    v0[m2] = tf32r(acc[t].z + be);
                    v1[m2] = tf32r(acc[t].w + bo);
                }
            }
        }
    }

    // zero sVt padding cols j in [49,60) (PV K-padding; p=0 there anyway)
    for (int idx = tid; idx < NHE * 32 * (VTST - NT); idx += 256) {
        const int jj = idx % (VTST - NT);
        const int dd = idx / (VTST - NT);
        sVt[dd * VTST + NT + jj] = 0.f;
    }
    __syncthreads();   // Q/K/Vt ready

    float* sO = sX;

    // ---------------- Phase 3: fragment attention ----------------------------
    #pragma unroll 1
    for (int uu = 0; uu < 2; uu++) {
        const int unit = warp * 2 + uu;      // (head, m-tile)
        const int h  = unit >> 2;
        const int mt = unit & 3;

        float4 s[7];
        #pragma unroll
        for (int nt = 0; nt < 7; nt++) s[nt] = make_float4(0.f, 0.f, 0.f, 0.f);

        const int r1 = min(h * NT + mt * 16 + gid,     NHE * NT - 1);
        const int r2 = min(h * NT + mt * 16 + gid + 8, NHE * NT - 1);
        int nrow[7];
        #pragma unroll
        for (int nt = 0; nt < 7; nt++)
            nrow[nt] = min(h * NT + nt * 8 + gid, NHE * NT - 1);

        // S = Q K^T
        #pragma unroll
        for (int kt = 0; kt < 4; kt++) {
            const int k0 = kt * 8 + tig;
            const uint32_t a0 = __float_as_uint(sQ[r1 * QKST + k0]);
            const uint32_t a1 = __float_as_uint(sQ[r2 * QKST + k0]);
            const uint32_t a2 = __float_as_uint(sQ[r1 * QKST + k0 + 4]);
            const uint32_t a3 = __float_as_uint(sQ[r2 * QKST + k0 + 4]);
            #pragma unroll
            for (int nt = 0; nt < 7; nt++) {
                const float* bp = sK + nrow[nt] * QKST + k0;
                mma_tf32(s[nt], a0, a1, a2, a3,
                         __float_as_uint(bp[0]), __float_as_uint(bp[4]));
            }
        }

        // + combined bias/mask
        const float* cb = g_cb + (((w256 * NHE + h) * CB_I) + mt * 16) * CB_J;
        #pragma unroll
        for (int nt = 0; nt < 7; nt++) {
            const int jc = nt * 8 + 2 * tig;
            const float2 c1 = *reinterpret_cast<const float2*>(cb + gid * CB_J + jc);
            const float2 c2 = *reinterpret_cast<const float2*>(cb + (gid + 8) * CB_J + jc);
            s[nt].x += c1.x; s[nt].y += c1.y; s[nt].z += c2.x; s[nt].w += c2.y;
        }

        // softmax over j (rows gid -> x/y, gid+8 -> z/w); quad reduce
        float mx1 = -3e38f, mx2 = -3e38f;
        #pragma unroll
        for (int nt = 0; nt < 7; nt++) {
            mx1 = fmaxf(mx1, fmaxf(s[nt].x, s[nt].y));
            mx2 = fmaxf(mx2, fmaxf(s[nt].z, s[nt].w));
        }
        mx1 = fmaxf(mx1, __shfl_xor_sync(FULLMASK, mx1, 1));
        mx1 = fmaxf(mx1, __shfl_xor_sync(FULLMASK, mx1, 2));
        mx2 = fmaxf(mx2, __shfl_xor_sync(FULLMASK, mx2, 1));
        mx2 = fmaxf(mx2, __shfl_xor_sync(FULLMASK, mx2, 2));

        float sm1 = 0.f, sm2 = 0.f;
        #pragma unroll
        for (int nt = 0; nt < 7; nt++) {
            s[nt].x = __expf(s[nt].x - mx1); s[nt].y = __expf(s[nt].y - mx1);
            s[nt].z = __expf(s[nt].z - mx2); s[nt].w = __expf(s[nt].w - mx2);
            sm1 += s[nt].x + s[nt].y;
            sm2 += s[nt].z + s[nt].w;
        }
        sm1 += __shfl_xor_sync(FULLMASK, sm1, 1);
        sm1 += __shfl_xor_sync(FULLMASK, sm1, 2);
        sm2 += __shfl_xor_sync(FULLMASK, sm2, 1);
        sm2 += __shfl_xor_sync(FULLMASK, sm2, 2);
        const float inv1 = __fdividef(1.f, sm1);
        const float inv2 = __fdividef(1.f, sm2);
        #pragma unroll
        for (int nt = 0; nt < 7; nt++) {
            s[nt].x = tf32r(s[nt].x * inv1); s[nt].y = tf32r(s[nt].y * inv1);
            s[nt].z = tf32r(s[nt].z * inv2); s[nt].w = tf32r(s[nt].w * inv2);
        }

        // O = P V : permute P into A-fragment layout via quad shuffles
        float4 o[4];
        #pragma unroll
        for (int nt = 0; nt < 4; nt++) o[nt] = make_float4(0.f, 0.f, 0.f, 0.f);

        const int  src1 = (lane & ~3) | (tig >> 1);
        const int  src2 = src1 + 2;
        const bool odd  = tig & 1;

        #pragma unroll
        for (int kt = 0; kt < 7; kt++) {
            const float x1 = __shfl_sync(FULLMASK, s[kt].x, src1);
            const float y1 = __shfl_sync(FULLMASK, s[kt].y, src1);
            const float z1 = __shfl_sync(FULLMASK, s[kt].z, src1);
            const float w1 = __shfl_sync(FULLMASK, s[kt].w, src1);
            const float x2 = __shfl_sync(FULLMASK, s[kt].x, src2);
            const float y2 = __shfl_sync(FULLMASK, s[kt].y, src2);
            const float z2 = __shfl_sync(FULLMASK, s[kt].z, src2);
            const float w2 = __shfl_sync(FULLMASK, s[kt].w, src2);
            const uint32_t a0 = __float_as_uint(odd ? y1 : x1);
            const uint32_t a1 = __float_as_uint(odd ? w1 : z1);
            const uint32_t a2 = __float_as_uint(odd ? y2 : x2);
            const uint32_t a3 = __float_as_uint(odd ? w2 : z2);
            #pragma unroll
            for (int nt = 0; nt < 4; nt++) {
                const float* vp = sVt + (h * 32 + nt * 8 + gid) * VTST + kt * 8 + tig;
                mma_tf32(o[nt], a0, a1, a2, a3,
                         __float_as_uint(vp[0]), __float_as_uint(vp[4]));
            }
        }

        // write attention output (tf32-rounded: proj GEMM A operand)
        const int i1r = mt * 16 + gid;
        const int i2r = i1r + 8;
        #pragma unroll
        for (int nt = 0; nt < 4; nt++) {
            const int d = h * 32 + nt * 8 + 2 * tig;
            if (i1r < NT)
                *reinterpret_cast<float2*>(sO + i1r * AST + d) =
                    make_float2(tf32r(o[nt].x), tf32r(o[nt].y));
            if (i2r < NT)
                *reinterpret_cast<float2*>(sO + i2r * AST + d) =
                    make_float2(tf32r(o[nt].z), tf32r(o[nt].w));
        }
    }

    // ---------------- Phase 4: proj GEMM (starts with syncthreads) -----------
    float4 acc[8];
    gemm_mma(sO, sWc, proj_w, warp, lane, tid, acc);

    float* sOut = sK;   // sK dead: stage proj output, stride AST
    #pragma unroll
    for (int t = 0; t < 8; t++) {
        const int ne = nn0 + t * 8 + 2 * tig;
        if (m1 < NT)
            *reinterpret_cast<float2*>(sOut + m1 * AST + ne) = make_float2(acc[t].x, acc[t].y);
        if (m2 < NT)
            *reinterpret_cast<float2*>(sOut + m2 * AST + ne) = make_float2(acc[t].z, acc[t].w);
    }
    __syncthreads();

    // ---------------- Phase 5: add bias, scatter (roll +SS) ------------------
    for (int idx = tid; idx < NT * (C / 4); idx += 256) {
        const int t  = idx >> 5;
        const int k4 = idx & 31;
        const int r  = t / 7;
        const int cc = t - r * 7;
        int gh = wh * WS + r + SS;  if (gh >= HHW) gh -= HHW;
        int gw = ww * WS + cc + SS; if (gw >= HHW) gw -= HHW;
        float4 v = *reinterpret_cast<const float4*>(sOut + t * AST + k4 * 4);
        const float4 pb = reinterpret_cast<const float4*>(proj_b)[k4];
        v.x += pb.x; v.y += pb.y; v.z += pb.z; v.w += pb.w;
        reinterpret_cast<float4*>(out + (size_t)(b * LROW + gh * HHW + gw) * C)[k4] = v;
    }
}

extern "C" void kernel_launch(void* const* d_in, const int* in_sizes, int n_in,
                              void* d_out, int out_size)
{
    (void)in_sizes; (void)n_in; (void)out_size;
    const float* x      = (const float*)d_in[0];
    const float* mask   = (const float*)d_in[1];
    const float* qkv_w  = (const float*)d_in[2];
    const float* qkv_b  = (const float*)d_in[3];
    const float* proj_w = (const float*)d_in[4];
    const float* proj_b = (const float*)d_in[5];
    const float* rpb    = (const float*)d_in[6];
    const int*   rel    = (const int*)d_in[7];
    float* out = (float*)d_out;

    cb_precompute<<<(CB_TOT + 255) / 256, 256>>>(mask, rpb, rel);

    cudaFuncSetAttribute(swin_block_kernel,
                         cudaFuncAttributeMaxDynamicSharedMemorySize, SMEM_BYTES);
    swin_block_kernel<<<2048, 256, SMEM_BYTES>>>(
        x, qkv_w, qkv_b, proj_w, proj_b, out);
}

// round 5
// speedup vs baseline: 4.5042x; 1.6541x over previous
#include <cuda_runtime.h>
#include <cuda_fp16.h>
#include <cstdint>

#define FULLMASK 0xffffffffu

namespace {
constexpr int C    = 128;
constexpr int NHE  = 4;
constexpr int WS   = 7;
constexpr int SS   = 3;
constexpr int NT   = 49;
constexpr int HHW  = 112;
constexpr int LROW = HHW * HHW;

// half-precision tile strides (in halves); b32 strides are /2
constexpr int XSTH  = 136;   // sXh / sOh row stride  (b32 stride 68  ≡ 4 mod 32)
constexpr int WSTH  = 136;   // sWh row stride        (b32 stride 68)
constexpr int QKSTH = 40;    // sQh / sKh row stride  (b32 stride 20)
constexpr int VTSTH = 72;    // sVth row stride       (b32 stride 36)

// byte offsets into dynamic smem
constexpr int XH_OFF = 0;                                  // 49 x 136 halves
constexpr int WH_OFF = XH_OFF + ((NT * XSTH * 2 + 15) & ~15);        // 13344
constexpr int QH_OFF = WH_OFF + C * WSTH * 2;                        // +34816
constexpr int KH_OFF = QH_OFF + NHE * NT * QKSTH * 2;                // +15680
constexpr int VT_OFF = KH_OFF + NHE * NT * QKSTH * 2;                // +15680
constexpr int SMEM_BYTES = VT_OFF + C * VTSTH * 2;                   // 97,952 B -> 2 CTAs/SM

constexpr float SCALE = 0.17677669529663689f;   // 1/sqrt(32)

constexpr int CB_I = 64;
constexpr int CB_J = 56;
constexpr int CB_TOT = 256 * NHE * CB_I * CB_J;
}  // namespace

__device__ float g_cb[CB_TOT];   // combined (mask + rel-pos bias) per window class

__device__ __forceinline__ uint32_t pkh2(float a, float b) {
    __half2 h = __floats2half2_rn(a, b);
    return *reinterpret_cast<uint32_t*>(&h);
}

__device__ __forceinline__
void mma_f16(float4& d, uint32_t a0, uint32_t a1, uint32_t a2, uint32_t a3,
             uint32_t b0, uint32_t b1)
{
    asm volatile(
        "mma.sync.aligned.m16n8k16.row.col.f32.f16.f16.f32 "
        "{%0,%1,%2,%3}, {%4,%5,%6,%7}, {%8,%9}, {%0,%1,%2,%3};\n"
        : "+f"(d.x), "+f"(d.y), "+f"(d.z), "+f"(d.w)
        : "r"(a0), "r"(a1), "r"(a2), "r"(a3), "r"(b0), "r"(b1));
}

// ---------------- bias precompute: g_cb[w][h][i][j] ----------------
__global__ void cb_precompute(const float* __restrict__ mask,
                              const float* __restrict__ rpb,
                              const int*   __restrict__ rel)
{
    const int idx = blockIdx.x * blockDim.x + threadIdx.x;
    if (idx >= CB_TOT) return;
    const int j = idx % CB_J;
    int r = idx / CB_J;
    const int i = r % CB_I;  r /= CB_I;
    const int h = r % NHE;
    const int w = r / NHE;
    float v;
    if (j >= NT)      v = -1e30f;
    else if (i >= NT) v = 0.f;
    else v = mask[(w * NT + i) * NT + j] + rpb[rel[i * NT + j] * NHE + h];
    g_cb[idx] = v;
}

// 49x128 @ 128x128^T fp16 GEMM. A in smem halves (b32 stride 68).
// W (fp32 gmem) staged fully into sWh once, then un-synced MMA sweep.
// Warp: m-tile = warp&3, n-half = (warp>>2)*64.
__device__ __forceinline__
void gemm_h(const uint32_t* __restrict__ sA32, uint32_t* __restrict__ sW32,
            const float4* __restrict__ wsrc4, int warp, int lane, int tid,
            float4 acc[8])
{
    #pragma unroll
    for (int t = 0; t < 8; t++) acc[t] = make_float4(0.f, 0.f, 0.f, 0.f);

    const int gid = lane >> 2;
    const int tig = lane & 3;
    const int mt  = warp & 3;
    const int n0  = (warp >> 2) * 64;

    int r1 = mt * 16 + gid;     if (r1 > NT - 1) r1 = NT - 1;
    int r2 = mt * 16 + gid + 8; if (r2 > NT - 1) r2 = NT - 1;
    const uint32_t* a1p = sA32 + r1 * 68 + tig;
    const uint32_t* a2p = sA32 + r2 * 68 + tig;

    __syncthreads();   // previous users of sWh done
    #pragma unroll
    for (int i = 0; i < 16; i++) {
        const int idx = tid + 256 * i;
        const int row = idx >> 5;
        const int q   = idx & 31;
        const float4 v = wsrc4[row * 32 + q];
        *reinterpret_cast<uint2*>(sW32 + row * 68 + q * 2) =
            make_uint2(pkh2(v.x, v.y), pkh2(v.z, v.w));
    }
    __syncthreads();

    #pragma unroll
    for (int ch = 0; ch < 8; ch++) {
        const uint32_t a0 = a1p[ch * 8];
        const uint32_t a1 = a2p[ch * 8];
        const uint32_t a2 = a1p[ch * 8 + 4];
        const uint32_t a3 = a2p[ch * 8 + 4];
        #pragma unroll
        for (int t = 0; t < 8; t++) {
            const uint32_t* bp = sW32 + (n0 + t * 8 + gid) * 68 + ch * 8 + tig;
            mma_f16(acc[t], a0, a1, a2, a3, bp[0], bp[4]);
        }
    }
}

__global__ __launch_bounds__(256, 2)
void swin_block_kernel(const float* __restrict__ x,
                       const float* __restrict__ qkv_w,
                       const float* __restrict__ qkv_b,
                       const float* __restrict__ proj_w,
                       const float* __restrict__ proj_b,
                       float* __restrict__ out)
{
    extern __shared__ char smb[];
    uint32_t* sX32 = reinterpret_cast<uint32_t*>(smb + XH_OFF);  // input/attn-out halves
    uint32_t* sW32 = reinterpret_cast<uint32_t*>(smb + WH_OFF);  // weight tile halves
    uint32_t* sQ32 = reinterpret_cast<uint32_t*>(smb + QH_OFF);
    uint32_t* sK32 = reinterpret_cast<uint32_t*>(smb + KH_OFF);
    uint32_t* sV32 = reinterpret_cast<uint32_t*>(smb + VT_OFF);  // V^T halves
    __half*   sVth = reinterpret_cast<__half*>(smb + VT_OFF);
    float*    sOut = reinterpret_cast<float*>(smb + QH_OFF);     // proj staging (fp32, stride 132)

    const int tid  = threadIdx.x;
    const int lane = tid & 31;
    const int warp = tid >> 5;
    const int gid  = lane >> 2;
    const int tig  = lane & 3;

    const int win  = blockIdx.x;
    const int b    = win >> 8;
    const int w256 = win & 255;
    const int wh   = w256 >> 4;
    const int ww   = w256 & 15;

    // ---------------- Phase 1: gather window (roll -SS), fp32 -> fp16 --------
    for (int idx = tid; idx < NT * (C / 4); idx += 256) {
        const int t  = idx >> 5;
        const int k4 = idx & 31;
        const int r  = t / 7;
        const int cc = t - r * 7;
        int gh = wh * WS + r + SS;  if (gh >= HHW) gh -= HHW;
        int gw = ww * WS + cc + SS; if (gw >= HHW) gw -= HHW;
        const float4 v = reinterpret_cast<const float4*>(
            x + (size_t)(b * LROW + gh * HHW + gw) * C)[k4];
        *reinterpret_cast<uint2*>(sX32 + t * 68 + k4 * 2) =
            make_uint2(pkh2(v.x, v.y), pkh2(v.z, v.w));
    }
    // zero V^T padding cols j in [49,72)
    for (int idx = tid; idx < C * (VTSTH - NT); idx += 256) {
        const int row = idx / (VTSTH - NT);
        const int cc  = NT + idx % (VTSTH - NT);
        sVth[row * VTSTH + cc] = __float2half_rn(0.f);
    }

    const int m1  = (warp & 3) * 16 + gid;
    const int m2  = m1 + 8;
    const int nn0 = (warp >> 2) * 64;

    // ---------------- Phase 2: QKV GEMMs (fp16 tensor cores) -----------------
    for (int tile = 0; tile < 3; tile++) {
        float4 acc[8];
        gemm_h(sX32, sW32, reinterpret_cast<const float4*>(qkv_w + tile * C * C),
               warp, lane, tid, acc);

        const float* bias = qkv_b + tile * C;
        #pragma unroll
        for (int t = 0; t < 8; t++) {
            const int ne = nn0 + t * 8 + 2 * tig;    // even feature index
            const int h  = ne >> 5;
            const int d  = ne & 31;
            const float be = __ldg(bias + ne);
            const float bo = __ldg(bias + ne + 1);
            if (tile == 0) {          // Q (unscaled; scale folded into softmax)
                if (m1 < NT)
                    sQ32[(h * NT + m1) * 20 + (d >> 1)] = pkh2(acc[t].x + be, acc[t].y + bo);
                if (m2 < NT)
                    sQ32[(h * NT + m2) * 20 + (d >> 1)] = pkh2(acc[t].z + be, acc[t].w + bo);
            } else if (tile == 1) {   // K
                if (m1 < NT)
                    sK32[(h * NT + m1) * 20 + (d >> 1)] = pkh2(acc[t].x + be, acc[t].y + bo);
                if (m2 < NT)
                    sK32[(h * NT + m2) * 20 + (d >> 1)] = pkh2(acc[t].z + be, acc[t].w + bo);
            } else {                  // V transposed: [h*32+d][j]
                __half* v0 = sVth + (h * 32 + d)     * VTSTH;
                __half* v1 = sVth + (h * 32 + d + 1) * VTSTH;
                if (m1 < NT) {
                    v0[m1] = __float2half_rn(acc[t].x + be);
                    v1[m1] = __float2half_rn(acc[t].y + bo);
                }
                if (m2 < NT) {
                    v0[m2] = __float2half_rn(acc[t].z + be);
                    v1[m2] = __float2half_rn(acc[t].w + bo);
                }
            }
        }
    }
    __syncthreads();   // Q/K/V^T ready

    // ---------------- Phase 3: fragment attention (fp16 mma) -----------------
    #pragma unroll 1
    for (int uu = 0; uu < 2; uu++) {
        const int unit = warp * 2 + uu;
        const int h  = unit >> 2;
        const int mt = unit & 3;

        float4 s[7];
        #pragma unroll
        for (int nt = 0; nt < 7; nt++) s[nt] = make_float4(0.f, 0.f, 0.f, 0.f);

        const int r1 = h * NT + min(mt * 16 + gid,     NT - 1);
        const int r2 = h * NT + min(mt * 16 + gid + 8, NT - 1);
        int nrow[7];
        #pragma unroll
        for (int nt = 0; nt < 7; nt++)
            nrow[nt] = h * NT + min(nt * 8 + gid, NT - 1);

        // S = Q K^T  (2 k16 chunks over head dim 32)
        #pragma unroll
        for (int kt = 0; kt < 2; kt++) {
            const uint32_t a0 = sQ32[r1 * 20 + kt * 8 + tig];
            const uint32_t a1 = sQ32[r2 * 20 + kt * 8 + tig];
            const uint32_t a2 = sQ32[r1 * 20 + kt * 8 + tig + 4];
            const uint32_t a3 = sQ32[r2 * 20 + kt * 8 + tig + 4];
            #pragma unroll
            for (int nt = 0; nt < 7; nt++) {
                const uint32_t* bp = sK32 + nrow[nt] * 20 + kt * 8 + tig;
                mma_f16(s[nt], a0, a1, a2, a3, bp[0], bp[4]);
            }
        }

        // s = s*SCALE + combined bias/mask (fp32 FFMA)
        const float* cb = g_cb + (((w256 * NHE + h) * CB_I) + mt * 16) * CB_J;
        #pragma unroll
        for (int nt = 0; nt < 7; nt++) {
            const int jc = nt * 8 + 2 * tig;
            const float2 c1 = *reinterpret_cast<const float2*>(cb + gid * CB_J + jc);
            const float2 c2 = *reinterpret_cast<const float2*>(cb + (gid + 8) * CB_J + jc);
            s[nt].x = fmaf(s[nt].x, SCALE, c1.x);
            s[nt].y = fmaf(s[nt].y, SCALE, c1.y);
            s[nt].z = fmaf(s[nt].z, SCALE, c2.x);
            s[nt].w = fmaf(s[nt].w, SCALE, c2.y);
        }

        // softmax over j (rows gid -> x/y, gid+8 -> z/w); quad reduce
        float mx1 = -3e38f, mx2 = -3e38f;
        #pragma unroll
        for (int nt = 0; nt < 7; nt++) {
            mx1 = fmaxf(mx1, fmaxf(s[nt].x, s[nt].y));
            mx2 = fmaxf(mx2, fmaxf(s[nt].z, s[nt].w));
        }
        mx1 = fmaxf(mx1, __shfl_xor_sync(FULLMASK, mx1, 1));
        mx1 = fmaxf(mx1, __shfl_xor_sync(FULLMASK, mx1, 2));
        mx2 = fmaxf(mx2, __shfl_xor_sync(FULLMASK, mx2, 1));
        mx2 = fmaxf(mx2, __shfl_xor_sync(FULLMASK, mx2, 2));

        float sm1 = 0.f, sm2 = 0.f;
        #pragma unroll
        for (int nt = 0; nt < 7; nt++) {
            s[nt].x = __expf(s[nt].x - mx1); s[nt].y = __expf(s[nt].y - mx1);
            s[nt].z = __expf(s[nt].z - mx2); s[nt].w = __expf(s[nt].w - mx2);
            sm1 += s[nt].x + s[nt].y;
            sm2 += s[nt].z + s[nt].w;
        }
        sm1 += __shfl_xor_sync(FULLMASK, sm1, 1);
        sm1 += __shfl_xor_sync(FULLMASK, sm1, 2);
        sm2 += __shfl_xor_sync(FULLMASK, sm2, 1);
        sm2 += __shfl_xor_sync(FULLMASK, sm2, 2);
        const float inv1 = __fdividef(1.f, sm1);
        const float inv2 = __fdividef(1.f, sm2);

        // pack P directly into fp16 A-fragments (no shuffles!)
        uint32_t pa[4][4];
        #pragma unroll
        for (int kt = 0; kt < 4; kt++) {
            const int n0t = 2 * kt;
            pa[kt][0] = pkh2(s[n0t].x * inv1, s[n0t].y * inv1);
            pa[kt][1] = pkh2(s[n0t].z * inv2, s[n0t].w * inv2);
            if (n0t + 1 < 7) {
                pa[kt][2] = pkh2(s[n0t + 1].x * inv1, s[n0t + 1].y * inv1);
                pa[kt][3] = pkh2(s[n0t + 1].z * inv2, s[n0t + 1].w * inv2);
            } else {
                pa[kt][2] = 0u; pa[kt][3] = 0u;
            }
        }

        // O = P V   (V^T in smem: B-frag pairs along j)
        float4 o[4];
        #pragma unroll
        for (int nt = 0; nt < 4; nt++) o[nt] = make_float4(0.f, 0.f, 0.f, 0.f);
        #pragma unroll
        for (int kt = 0; kt < 4; kt++) {
            #pragma unroll
            for (int nt = 0; nt < 4; nt++) {
                const uint32_t* bp = sV32 + (h * 32 + nt * 8 + gid) * 36 + kt * 8 + tig;
                mma_f16(o[nt], pa[kt][0], pa[kt][1], pa[kt][2], pa[kt][3], bp[0], bp[4]);
            }
        }

        // write attention output as halves (proj GEMM A operand)
        const int i1r = mt * 16 + gid;
        const int i2r = i1r + 8;
        #pragma unroll
        for (int nt = 0; nt < 4; nt++) {
            const int col = h * 32 + nt * 8 + 2 * tig;
            if (i1r < NT) sX32[i1r * 68 + (col >> 1)] = pkh2(o[nt].x, o[nt].y);
            if (i2r < NT) sX32[i2r * 68 + (col >> 1)] = pkh2(o[nt].z, o[nt].w);
        }
    }

    // ---------------- Phase 4: proj GEMM (internal syncs order sOh) ----------
    float4 acc[8];
    gemm_h(sX32, sW32, reinterpret_cast<const float4*>(proj_w), warp, lane, tid, acc);

    // stage fp32 result over dead sQ/sK region (stride 132 floats)
    #pragma unroll
    for (int t = 0; t < 8; t++) {
        const int ne = nn0 + t * 8 + 2 * tig;
        if (m1 < NT)
            *reinterpret_cast<float2*>(sOut + m1 * 132 + ne) = make_float2(acc[t].x, acc[t].y);
        if (m2 < NT)
            *reinterpret_cast<float2*>(sOut + m2 * 132 + ne) = make_float2(acc[t].z, acc[t].w);
    }
    __syncthreads();

    // ---------------- Phase 5: add bias, scatter (roll +SS) ------------------
    for (int idx = tid; idx < NT * (C / 4); idx += 256) {
        const int t  = idx >> 5;
        const int k4 = idx & 31;
        const int r  = t / 7;
        const int cc = t - r * 7;
        int gh = wh * WS + r + SS;  if (gh >= HHW) gh -= HHW;
        int gw = ww * WS + cc + SS; if (gw >= HHW) gw -= HHW;
        float4 v = *reinterpret_cast<const float4*>(sOut + t * 132 + k4 * 4);
        const float4 pb = reinterpret_cast<const float4*>(proj_b)[k4];
        v.x += pb.x; v.y += pb.y; v.z += pb.z; v.w += pb.w;
        reinterpret_cast<float4*>(out + (size_t)(b * LROW + gh * HHW + gw) * C)[k4] = v;
    }
}

extern "C" void kernel_launch(void* const* d_in, const int* in_sizes, int n_in,
                              void* d_out, int out_size)
{
    (void)in_sizes; (void)n_in; (void)out_size;
    const float* x      = (const float*)d_in[0];
    const float* mask   = (const float*)d_in[1];
    const float* qkv_w  = (const float*)d_in[2];
    const float* qkv_b  = (const float*)d_in[3];
    const float* proj_w = (const float*)d_in[4];
    const float* proj_b = (const float*)d_in[5];
    const float* rpb    = (const float*)d_in[6];
    const int*   rel    = (const int*)d_in[7];
    float* out = (float*)d_out;

    cb_precompute<<<(CB_TOT + 255) / 256, 256>>>(mask, rpb, rel);

    cudaFuncSetAttribute(swin_block_kernel,
                         cudaFuncAttributeMaxDynamicSharedMemorySize, SMEM_BYTES);
    swin_block_kernel<<<2048, 256, SMEM_BYTES>>>(
        x, qkv_w, qkv_b, proj_w, proj_b, out);
}

// round 6
// speedup vs baseline: 4.9453x; 1.0979x over previous
#include <cuda_runtime.h>
#include <cuda_fp16.h>
#include <cstdint>

#define FULLMASK 0xffffffffu

namespace {
constexpr int C    = 128;
constexpr int NHE  = 4;
constexpr int WS   = 7;
constexpr int SS   = 3;
constexpr int NT   = 49;
constexpr int HHW  = 112;
constexpr int LROW = HHW * HHW;

// half-precision tile strides (in halves); b32 strides are /2
constexpr int XSTH  = 136;   // sXh / sOh row stride  (b32 stride 68)
constexpr int WSTH  = 136;   // sWh row stride        (b32 stride 68)
constexpr int QKSTH = 40;    // sQh / sKh row stride  (b32 stride 20)
constexpr int VTSTH = 72;    // sVth row stride       (b32 stride 36)

// byte offsets into dynamic smem
constexpr int XH_OFF = 0;                                            // 49 x 136 halves
constexpr int WH_OFF = XH_OFF + ((NT * XSTH * 2 + 15) & ~15);
constexpr int QH_OFF = WH_OFF + C * WSTH * 2;
constexpr int KH_OFF = QH_OFF + NHE * NT * QKSTH * 2;
constexpr int VT_OFF = KH_OFF + NHE * NT * QKSTH * 2;
constexpr int SMEM_BYTES = VT_OFF + C * VTSTH * 2;                   // 97,952 B -> 2 CTAs/SM

constexpr float SCALE = 0.17677669529663689f;   // 1/sqrt(32)

constexpr int CB_I = 64;
constexpr int CB_J = 56;
constexpr int CB_TOT = 256 * NHE * CB_I * CB_J;

constexpr int WQKV_ELEMS  = 3 * C * C;   // 49152
constexpr int WPROJ_ELEMS = C * C;       // 16384
}  // namespace

__device__ float  g_cb[CB_TOT];          // combined (mask + rel-pos bias)
__device__ __half g_wqkv[WQKV_ELEMS];    // qkv_w pre-converted to fp16
__device__ __half g_wproj[WPROJ_ELEMS];  // proj_w pre-converted to fp16

__device__ __forceinline__ uint32_t pkh2(float a, float b) {
    __half2 h = __floats2half2_rn(a, b);
    return *reinterpret_cast<uint32_t*>(&h);
}

__device__ __forceinline__
void mma_f16(float4& d, uint32_t a0, uint32_t a1, uint32_t a2, uint32_t a3,
             uint32_t b0, uint32_t b1)
{
    asm volatile(
        "mma.sync.aligned.m16n8k16.row.col.f32.f16.f16.f32 "
        "{%0,%1,%2,%3}, {%4,%5,%6,%7}, {%8,%9}, {%0,%1,%2,%3};\n"
        : "+f"(d.x), "+f"(d.y), "+f"(d.z), "+f"(d.w)
        : "r"(a0), "r"(a1), "r"(a2), "r"(a3), "r"(b0), "r"(b1));
}

// ---------------- precompute: combined bias + fp16 weights ----------------
__global__ void cb_precompute(const float* __restrict__ mask,
                              const float* __restrict__ rpb,
                              const int*   __restrict__ rel,
                              const float* __restrict__ qkv_w,
                              const float* __restrict__ proj_w)
{
    const int idx = blockIdx.x * blockDim.x + threadIdx.x;
    // weight fp16 conversion
    if (idx < WQKV_ELEMS)  g_wqkv[idx]  = __float2half_rn(qkv_w[idx]);
    if (idx < WPROJ_ELEMS) g_wproj[idx] = __float2half_rn(proj_w[idx]);
    if (idx >= CB_TOT) return;
    const int j = idx % CB_J;
    int r = idx / CB_J;
    const int i = r % CB_I;  r /= CB_I;
    const int h = r % NHE;
    const int w = r / NHE;
    float v;
    if (j >= NT)      v = -1e30f;
    else if (i >= NT) v = 0.f;
    else v = mask[(w * NT + i) * NT + j] + rpb[rel[i * NT + j] * NHE + h];
    g_cb[idx] = v;
}

// 49x128 @ 128x128^T fp16 GEMM. A in smem halves (b32 stride 68).
// W already fp16 in gmem; staged fully into sWh (8 LDG.128 + 8 STS.128 / thread).
__device__ __forceinline__
void gemm_h(const uint32_t* __restrict__ sA32, uint32_t* __restrict__ sW32,
            const uint4* __restrict__ w4, int warp, int lane, int tid,
            float4 acc[8])
{
    #pragma unroll
    for (int t = 0; t < 8; t++) acc[t] = make_float4(0.f, 0.f, 0.f, 0.f);

    const int gid = lane >> 2;
    const int tig = lane & 3;
    const int mt  = warp & 3;
    const int n0  = (warp >> 2) * 64;

    int r1 = mt * 16 + gid;     if (r1 > NT - 1) r1 = NT - 1;
    int r2 = mt * 16 + gid + 8; if (r2 > NT - 1) r2 = NT - 1;
    const uint32_t* a1p = sA32 + r1 * 68 + tig;
    const uint32_t* a2p = sA32 + r2 * 68 + tig;

    __syncthreads();   // previous users of sWh done
    #pragma unroll
    for (int i = 0; i < 8; i++) {
        const int idx = tid + 256 * i;      // 2048 uint4 total
        const int row = idx >> 4;           // 16 uint4 per 128-half row
        const int q   = idx & 15;
        *reinterpret_cast<uint4*>(sW32 + row * 68 + q * 4) = w4[idx];
    }
    __syncthreads();

    #pragma unroll
    for (int ch = 0; ch < 8; ch++) {
        const uint32_t a0 = a1p[ch * 8];
        const uint32_t a1 = a2p[ch * 8];
        const uint32_t a2 = a1p[ch * 8 + 4];
        const uint32_t a3 = a2p[ch * 8 + 4];
        #pragma unroll
        for (int t = 0; t < 8; t++) {
            const uint32_t* bp = sW32 + (n0 + t * 8 + gid) * 68 + ch * 8 + tig;
            mma_f16(acc[t], a0, a1, a2, a3, bp[0], bp[4]);
        }
    }
}

__global__ __launch_bounds__(256, 2)
void swin_block_kernel(const float* __restrict__ x,
                       const float* __restrict__ qkv_b,
                       const float* __restrict__ proj_b,
                       float* __restrict__ out)
{
    extern __shared__ char smb[];
    uint32_t* sX32 = reinterpret_cast<uint32_t*>(smb + XH_OFF);  // input/attn-out halves
    uint32_t* sW32 = reinterpret_cast<uint32_t*>(smb + WH_OFF);  // weight tile halves
    uint32_t* sQ32 = reinterpret_cast<uint32_t*>(smb + QH_OFF);
    uint32_t* sK32 = reinterpret_cast<uint32_t*>(smb + KH_OFF);
    uint32_t* sV32 = reinterpret_cast<uint32_t*>(smb + VT_OFF);  // V^T halves
    __half*   sVth = reinterpret_cast<__half*>(smb + VT_OFF);
    float*    sOut = reinterpret_cast<float*>(smb + QH_OFF);     // proj staging (fp32, stride 132)

    const int tid  = threadIdx.x;
    const int lane = tid & 31;
    const int warp = tid >> 5;
    const int gid  = lane >> 2;
    const int tig  = lane & 3;

    const int win  = blockIdx.x;
    const int b    = win >> 8;
    const int w256 = win & 255;
    const int wh   = w256 >> 4;
    const int ww   = w256 & 15;

    // ---------------- Phase 1: gather window (roll -SS), fp32 -> fp16 --------
    for (int idx = tid; idx < NT * (C / 4); idx += 256) {
        const int t  = idx >> 5;
        const int k4 = idx & 31;
        const int r  = t / 7;
        const int cc = t - r * 7;
        int gh = wh * WS + r + SS;  if (gh >= HHW) gh -= HHW;
        int gw = ww * WS + cc + SS; if (gw >= HHW) gw -= HHW;
        const float4 v = reinterpret_cast<const float4*>(
            x + (size_t)(b * LROW + gh * HHW + gw) * C)[k4];
        *reinterpret_cast<uint2*>(sX32 + t * 68 + k4 * 2) =
            make_uint2(pkh2(v.x, v.y), pkh2(v.z, v.w));
    }
    // zero V^T padding cols j in [49,72)
    for (int idx = tid; idx < C * (VTSTH - NT); idx += 256) {
        const int row = idx / (VTSTH - NT);
        const int cc  = NT + idx % (VTSTH - NT);
        sVth[row * VTSTH + cc] = __float2half_rn(0.f);
    }

    const int m1  = (warp & 3) * 16 + gid;
    const int m2  = m1 + 8;
    const int nn0 = (warp >> 2) * 64;

    // ---------------- Phase 2: QKV GEMMs (fp16 tensor cores) -----------------
    for (int tile = 0; tile < 3; tile++) {
        float4 acc[8];
        gemm_h(sX32, sW32,
               reinterpret_cast<const uint4*>(g_wqkv + tile * C * C),
               warp, lane, tid, acc);

        const float* bias = qkv_b + tile * C;
        #pragma unroll
        for (int t = 0; t < 8; t++) {
            const int ne = nn0 + t * 8 + 2 * tig;    // even feature index
            const int h  = ne >> 5;
            const int d  = ne & 31;
            const float be = __ldg(bias + ne);
            const float bo = __ldg(bias + ne + 1);
            if (tile == 0) {          // Q (scale folded into softmax)
                if (m1 < NT)
                    sQ32[(h * NT + m1) * 20 + (d >> 1)] = pkh2(acc[t].x + be, acc[t].y + bo);
                if (m2 < NT)
                    sQ32[(h * NT + m2) * 20 + (d >> 1)] = pkh2(acc[t].z + be, acc[t].w + bo);
            } else if (tile == 1) {   // K
                if (m1 < NT)
                    sK32[(h * NT + m1) * 20 + (d >> 1)] = pkh2(acc[t].x + be, acc[t].y + bo);
                if (m2 < NT)
                    sK32[(h * NT + m2) * 20 + (d >> 1)] = pkh2(acc[t].z + be, acc[t].w + bo);
            } else {                  // V transposed: [h*32+d][j]
                __half* v0 = sVth + (h * 32 + d)     * VTSTH;
                __half* v1 = sVth + (h * 32 + d + 1) * VTSTH;
                if (m1 < NT) {
                    v0[m1] = __float2half_rn(acc[t].x + be);
                    v1[m1] = __float2half_rn(acc[t].y + bo);
                }
                if (m2 < NT) {
                    v0[m2] = __float2half_rn(acc[t].z + be);
                    v1[m2] = __float2half_rn(acc[t].w + bo);
                }
            }
        }
    }
    __syncthreads();   // Q/K/V^T ready

    // ---------------- Phase 3: fragment attention (fp16 mma) -----------------
    #pragma unroll 1
    for (int uu = 0; uu < 2; uu++) {
        const int unit = warp * 2 + uu;
        const int h  = unit >> 2;
        const int mt = unit & 3;

        float4 s[7];
        #pragma unroll
        for (int nt = 0; nt < 7; nt++) s[nt] = make_float4(0.f, 0.f, 0.f, 0.f);

        const int r1 = h * NT + min(mt * 16 + gid,     NT - 1);
        const int r2 = h * NT + min(mt * 16 + gid + 8, NT - 1);
        int nrow[7];
        #pragma unroll
        for (int nt = 0; nt < 7; nt++)
            nrow[nt] = h * NT + min(nt * 8 + gid, NT - 1);

        // S = Q K^T  (2 k16 chunks over head dim 32)
        #pragma unroll
        for (int kt = 0; kt < 2; kt++) {
            const uint32_t a0 = sQ32[r1 * 20 + kt * 8 + tig];
            const uint32_t a1 = sQ32[r2 * 20 + kt * 8 + tig];
            const uint32_t a2 = sQ32[r1 * 20 + kt * 8 + tig + 4];
            const uint32_t a3 = sQ32[r2 * 20 + kt * 8 + tig + 4];
            #pragma unroll
            for (int nt = 0; nt < 7; nt++) {
                const uint32_t* bp = sK32 + nrow[nt] * 20 + kt * 8 + tig;
                mma_f16(s[nt], a0, a1, a2, a3, bp[0], bp[4]);
            }
        }

        // s = s*SCALE + combined bias/mask (fp32 FFMA)
        const float* cb = g_cb + (((w256 * NHE + h) * CB_I) + mt * 16) * CB_J;
        #pragma unroll
        for (int nt = 0; nt < 7; nt++) {
            const int jc = nt * 8 + 2 * tig;
            const float2 c1 = *reinterpret_cast<const float2*>(cb + gid * CB_J + jc);
            const float2 c2 = *reinterpret_cast<const float2*>(cb + (gid + 8) * CB_J + jc);
            s[nt].x = fmaf(s[nt].x, SCALE, c1.x);
            s[nt].y = fmaf(s[nt].y, SCALE, c1.y);
            s[nt].z = fmaf(s[nt].z, SCALE, c2.x);
            s[nt].w = fmaf(s[nt].w, SCALE, c2.y);
        }

        // softmax over j; quad reduce
        float mx1 = -3e38f, mx2 = -3e38f;
        #pragma unroll
        for (int nt = 0; nt < 7; nt++) {
            mx1 = fmaxf(mx1, fmaxf(s[nt].x, s[nt].y));
            mx2 = fmaxf(mx2, fmaxf(s[nt].z, s[nt].w));
        }
        mx1 = fmaxf(mx1, __shfl_xor_sync(FULLMASK, mx1, 1));
        mx1 = fmaxf(mx1, __shfl_xor_sync(FULLMASK, mx1, 2));
        mx2 = fmaxf(mx2, __shfl_xor_sync(FULLMASK, mx2, 1));
        mx2 = fmaxf(mx2, __shfl_xor_sync(FULLMASK, mx2, 2));

        float sm1 = 0.f, sm2 = 0.f;
        #pragma unroll
        for (int nt = 0; nt < 7; nt++) {
            s[nt].x = __expf(s[nt].x - mx1); s[nt].y = __expf(s[nt].y - mx1);
            s[nt].z = __expf(s[nt].z - mx2); s[nt].w = __expf(s[nt].w - mx2);
            sm1 += s[nt].x + s[nt].y;
            sm2 += s[nt].z + s[nt].w;
        }
        sm1 += __shfl_xor_sync(FULLMASK, sm1, 1);
        sm1 += __shfl_xor_sync(FULLMASK, sm1, 2);
        sm2 += __shfl_xor_sync(FULLMASK, sm2, 1);
        sm2 += __shfl_xor_sync(FULLMASK, sm2, 2);
        const float inv1 = __fdividef(1.f, sm1);
        const float inv2 = __fdividef(1.f, sm2);

        // pack P directly into fp16 A-fragments (no shuffles)
        uint32_t pa[4][4];
        #pragma unroll
        for (int kt = 0; kt < 4; kt++) {
            const int n0t = 2 * kt;
            pa[kt][0] = pkh2(s[n0t].x * inv1, s[n0t].y * inv1);
            pa[kt][1] = pkh2(s[n0t].z * inv2, s[n0t].w * inv2);
            if (n0t + 1 < 7) {
                pa[kt][2] = pkh2(s[n0t + 1].x * inv1, s[n0t + 1].y * inv1);
                pa[kt][3] = pkh2(s[n0t + 1].z * inv2, s[n0t + 1].w * inv2);
            } else {
                pa[kt][2] = 0u; pa[kt][3] = 0u;
            }
        }

        // O = P V   (V^T in smem)
        float4 o[4];
        #pragma unroll
        for (int nt = 0; nt < 4; nt++) o[nt] = make_float4(0.f, 0.f, 0.f, 0.f);
        #pragma unroll
        for (int kt = 0; kt < 4; kt++) {
            #pragma unroll
            for (int nt = 0; nt < 4; nt++) {
                const uint32_t* bp = sV32 + (h * 32 + nt * 8 + gid) * 36 + kt * 8 + tig;
                mma_f16(o[nt], pa[kt][0], pa[kt][1], pa[kt][2], pa[kt][3], bp[0], bp[4]);
            }
        }

        // write attention output as halves (proj GEMM A operand)
        const int i1r = mt * 16 + gid;
        const int i2r = i1r + 8;
        #pragma unroll
        for (int nt = 0; nt < 4; nt++) {
            const int col = h * 32 + nt * 8 + 2 * tig;
            if (i1r < NT) sX32[i1r * 68 + (col >> 1)] = pkh2(o[nt].x, o[nt].y);
            if (i2r < NT) sX32[i2r * 68 + (col >> 1)] = pkh2(o[nt].z, o[nt].w);
        }
    }

    // ---------------- Phase 4: proj GEMM (internal syncs order sOh) ----------
    float4 acc[8];
    gemm_h(sX32, sW32, reinterpret_cast<const uint4*>(g_wproj),
           warp, lane, tid, acc);

    // stage fp32 result over dead sQ/sK region (stride 132 floats)
    #pragma unroll
    for (int t = 0; t < 8; t++) {
        const int ne = nn0 + t * 8 + 2 * tig;
        if (m1 < NT)
            *reinterpret_cast<float2*>(sOut + m1 * 132 + ne) = make_float2(acc[t].x, acc[t].y);
        if (m2 < NT)
            *reinterpret_cast<float2*>(sOut + m2 * 132 + ne) = make_float2(acc[t].z, acc[t].w);
    }
    __syncthreads();

    // ---------------- Phase 5: add bias, scatter (roll +SS) ------------------
    for (int idx = tid; idx < NT * (C / 4); idx += 256) {
        const int t  = idx >> 5;
        const int k4 = idx & 31;
        const int r  = t / 7;
        const int cc = t - r * 7;
        int gh = wh * WS + r + SS;  if (gh >= HHW) gh -= HHW;
        int gw = ww * WS + cc + SS; if (gw >= HHW) gw -= HHW;
        float4 v = *reinterpret_cast<const float4*>(sOut + t * 132 + k4 * 4);
        const float4 pb = reinterpret_cast<const float4*>(proj_b)[k4];
        v.x += pb.x; v.y += pb.y; v.z += pb.z; v.w += pb.w;
        reinterpret_cast<float4*>(out + (size_t)(b * LROW + gh * HHW + gw) * C)[k4] = v;
    }
}

extern "C" void kernel_launch(void* const* d_in, const int* in_sizes, int n_in,
                              void* d_out, int out_size)
{
    (void)in_sizes; (void)n_in; (void)out_size;
    const float* x      = (const float*)d_in[0];
    const float* mask   = (const float*)d_in[1];
    const float* qkv_w  = (const float*)d_in[2];
    const float* qkv_b  = (const float*)d_in[3];
    const float* proj_w = (const float*)d_in[4];
    const float* proj_b = (const float*)d_in[5];
    const float* rpb    = (const float*)d_in[6];
    const int*   rel    = (const int*)d_in[7];
    float* out = (float*)d_out;

    cb_precompute<<<(CB_TOT + 255) / 256, 256>>>(mask, rpb, rel, qkv_w, proj_w);

    cudaFuncSetAttribute(swin_block_kernel,
                         cudaFuncAttributeMaxDynamicSharedMemorySize, SMEM_BYTES);
    swin_block_kernel<<<2048, 256, SMEM_BYTES>>>(x, qkv_b, proj_b, out);
}